// round 16
// baseline (speedup 1.0000x reference)
#include <cuda_runtime.h>
#include <math.h>

#define BATCH 8
#define NPTS  4096
#define HH    256
#define KOUT  1024
#define CAPH  256           // per-cluster smem capacity (E[cnt]=64 -> 24 sigma)

// ---------------------------------------------------------------------------
// Single kernel, 256 blocks = 8 batches x 32 cluster-PAIR blocks.
// Block (b,c) owns clusters {2c, 2c+1}; membership test for the pair is ONE
// compare: ((unsigned)l >> 1) == c  (noise l=-1 can never match).
// Block c==31 owns cluster 62 + noise rows (label 63 never occurs -> side-1
// list empty -> warps 4-7 free for the noise constant path).
// Noise rows: ctx is zeroed AFTER the v-projection, so o = bo exactly.
// Phase 1: bitmask scan -> two member/query lists (side = lab[n] & 1).
// Phase 2: parallel gather of member x into smem halves.
// Phase 3: warps 0-3 -> cluster 2c, warps 4-7 -> 2c+1; dual-query rounds,
//          packed-f4 MLP, xor-butterfly reductions. Pre-folded weights:
//   score(x_m) = qk·x_m + qb,   qk = M·x_q + u,  qb = wb·x_q + s0
//   o          = N·mean + p     (valid queries; k/v/ctx never materialized)
// ---------------------------------------------------------------------------
__global__ __launch_bounds__(256, 4)
void fused_kernel(const float* __restrict__ x,
                  const int*   __restrict__ labels,
                  const float* __restrict__ Wq, const float* __restrict__ bq,
                  const float* __restrict__ Wk, const float* __restrict__ bk,
                  const float* __restrict__ Wv, const float* __restrict__ bv,
                  const float* __restrict__ Wo, const float* __restrict__ bo,
                  const float* __restrict__ W1, const float* __restrict__ b1,
                  const float* __restrict__ W2, const float* __restrict__ b2,
                  float* __restrict__ out)
{
    __shared__ float4 sx[2 * CAPH];       // member x; [0,256) side0, [256,512) side1
    __shared__ short  smidx[2 * CAPH];    // member original row n
    __shared__ int    sq[2 * CAPH];       // (sx idx << 16) | query row n, per side
    __shared__ float4 sW1p[HH];           // (W1[3j], W1[3j+1], W1[3j+2], b1[j])
    __shared__ float4 sW2p[HH];           // (W2[j], W2[HH+j], W2[2HH+j], 0)
    __shared__ float  sM[9], su[3], swb[3], sNw[9], sp[3], s_s0;
    __shared__ int    s_cnt0, s_cnt1, s_qn0, s_qn1;
    __shared__ float  s_y3[3];

    const int tid  = threadIdx.x;
    const int warp = tid >> 5;
    const int lane = tid & 31;
    const int b    = blockIdx.x >> 5;
    const int c    = blockIdx.x & 31;     // cluster pair {2c, 2c+1}

    const int*   lab = labels + b * NPTS;
    const float* xb  = x + (size_t)b * NPTS * 3;

    // Stage MLP weights packed (one j per thread; 256 == HH)
    {
        const int j = tid;
        sW1p[j] = make_float4(W1[3*j], W1[3*j+1], W1[3*j+2], b1[j]);
        sW2p[j] = make_float4(W2[j], W2[HH + j], W2[2*HH + j], 0.f);
    }
    if (tid == 0) { s_cnt0 = 0; s_cnt1 = 0; s_qn0 = 0; s_qn1 = 0; }
    __syncthreads();

    // Phase 1: one-compare pair scan (bit bi = t*4+j -> row t*1024 + tid*4 + j)
    const int4* lab4 = reinterpret_cast<const int4*>(lab);
    unsigned mask = 0;
#pragma unroll
    for (int t = 0; t < 4; t++) {
        const int4 L = lab4[t * 256 + tid];
        mask |= (unsigned)(((unsigned)L.x >> 1) == (unsigned)c) << (t * 4 + 0);
        mask |= (unsigned)(((unsigned)L.y >> 1) == (unsigned)c) << (t * 4 + 1);
        mask |= (unsigned)(((unsigned)L.z >> 1) == (unsigned)c) << (t * 4 + 2);
        mask |= (unsigned)(((unsigned)L.w >> 1) == (unsigned)c) << (t * 4 + 3);
    }
    const int nbase = tid * 4;
    while (mask) {
        const int bi = __ffs(mask) - 1;
        mask &= mask - 1;
        const int n    = ((bi >> 2) << 10) + nbase + (bi & 3);
        const int side = lab[n] & 1;                      // L1-hit reload
        const int p    = atomicAdd(side ? &s_cnt1 : &s_cnt0, 1);
        if (p < CAPH) {
            const int idx = side * CAPH + p;
            smidx[idx] = (short)n;
            if (bi < 4) {                                 // bi<4 <=> n < KOUT
                const int qp = atomicAdd(side ? &s_qn1 : &s_qn0, 1);
                sq[side * CAPH + qp] = n | (idx << 16);
            }
        }
    }

    // Parallel prefold: 28 threads, one folded scalar each.
    if (tid < 28) {
        const float scale = 0.57735026919f;   // 1/sqrt(3)
        const int i = tid;
        if (i < 9) {
            int cc = i / 3, d = i % 3;
            sM[i] = scale * (__ldg(Wq+d)  *__ldg(Wk+cc)
                           + __ldg(Wq+3+d)*__ldg(Wk+3+cc)
                           + __ldg(Wq+6+d)*__ldg(Wk+6+cc));
        } else if (i < 12) {
            int cc = i - 9;
            su[cc] = scale * (__ldg(bq+0)*__ldg(Wk+cc)
                            + __ldg(bq+1)*__ldg(Wk+3+cc)
                            + __ldg(bq+2)*__ldg(Wk+6+cc));
        } else if (i < 15) {
            int cc = i - 12;
            swb[cc] = scale * (__ldg(bk+0)*__ldg(Wq+cc)
                             + __ldg(bk+1)*__ldg(Wq+3+cc)
                             + __ldg(bk+2)*__ldg(Wq+6+cc));
        } else if (i == 15) {
            s_s0 = scale * (__ldg(bk+0)*__ldg(bq+0)
                          + __ldg(bk+1)*__ldg(bq+1)
                          + __ldg(bk+2)*__ldg(bq+2));
        } else if (i < 25) {
            int r = (i - 16) / 3, cc = (i - 16) % 3;
            sNw[i-16] = __ldg(Wo+r*3+0)*__ldg(Wv+cc)
                      + __ldg(Wo+r*3+1)*__ldg(Wv+3+cc)
                      + __ldg(Wo+r*3+2)*__ldg(Wv+6+cc);
        } else {
            int r = i - 25;
            sp[r] = __ldg(Wo+r*3+0)*__ldg(bv+0)
                  + __ldg(Wo+r*3+1)*__ldg(bv+1)
                  + __ldg(Wo+r*3+2)*__ldg(bv+2) + __ldg(bo+r);
        }
    }
    __syncthreads();

    const int cnt0 = min(s_cnt0, CAPH);
    const int cnt1 = min(s_cnt1, CAPH);

    // Phase 2: pure parallel gather of member x (no atomics)
    for (int i = tid; i < cnt0; i += 256) {
        const float* xv = xb + (size_t)smidx[i] * 3;
        sx[i] = make_float4(xv[0], xv[1], xv[2], 0.f);
    }
    for (int i = tid; i < cnt1; i += 256) {
        const float* xv = xb + (size_t)smidx[CAPH + i] * 3;
        sx[CAPH + i] = make_float4(xv[0], xv[1], xv[2], 0.f);
    }
    __syncthreads();

    const float b20 = __ldg(b2 + 0), b21 = __ldg(b2 + 1), b22 = __ldg(b2 + 2);

    // Phase 3: warps 0-3 -> side 0, warps 4-7 -> side 1; dual-query rounds.
    const int side  = warp >> 2;
    const int qn    = side ? s_qn1 : s_qn0;
    const int cnt   = side ? cnt1 : cnt0;
    const int sbase = side * CAPH;

    for (int qq = (warp & 3) * 2; qq < qn; qq += 8) {
        const int  e0   = sq[sbase + qq];
        const bool has2 = (qq + 1) < qn;
        const int  e1   = has2 ? sq[sbase + qq + 1] : e0;
        const int  n0q  = e0 & 0xFFFF, p0 = e0 >> 16;
        const int  n1q  = e1 & 0xFFFF, p1 = e1 >> 16;

        const float4 xqa = sx[p0];
        const float4 xqb = sx[p1];

        const float qkA0 = fmaf(sM[0], xqa.x, fmaf(sM[1], xqa.y, fmaf(sM[2], xqa.z, su[0])));
        const float qkA1 = fmaf(sM[3], xqa.x, fmaf(sM[4], xqa.y, fmaf(sM[5], xqa.z, su[1])));
        const float qkA2 = fmaf(sM[6], xqa.x, fmaf(sM[7], xqa.y, fmaf(sM[8], xqa.z, su[2])));
        const float qbA  = fmaf(swb[0], xqa.x, fmaf(swb[1], xqa.y, fmaf(swb[2], xqa.z, s_s0)));
        const float qkB0 = fmaf(sM[0], xqb.x, fmaf(sM[1], xqb.y, fmaf(sM[2], xqb.z, su[0])));
        const float qkB1 = fmaf(sM[3], xqb.x, fmaf(sM[4], xqb.y, fmaf(sM[5], xqb.z, su[1])));
        const float qkB2 = fmaf(sM[6], xqb.x, fmaf(sM[7], xqb.y, fmaf(sM[8], xqb.z, su[2])));
        const float qbB  = fmaf(swb[0], xqb.x, fmaf(swb[1], xqb.y, fmaf(swb[2], xqb.z, s_s0)));

        // dual plain-exp softmax; one sx load feeds both queries
        float smA = 0.f, aA0 = 0.f, aA1 = 0.f, aA2 = 0.f;
        float smB = 0.f, aB0 = 0.f, aB1 = 0.f, aB2 = 0.f;
        for (int i = lane; i < cnt; i += 32) {
            const float4 xm = sx[sbase + i];
            const float sA = fmaf(qkA0, xm.x, fmaf(qkA1, xm.y, fmaf(qkA2, xm.z, qbA)));
            const float sB = fmaf(qkB0, xm.x, fmaf(qkB1, xm.y, fmaf(qkB2, xm.z, qbB)));
            const float eA = __expf(sA);
            const float eB = __expf(sB);
            smA += eA; smB += eB;
            aA0 = fmaf(eA, xm.x, aA0); aB0 = fmaf(eB, xm.x, aB0);
            aA1 = fmaf(eA, xm.y, aA1); aB1 = fmaf(eB, xm.y, aB1);
            aA2 = fmaf(eA, xm.z, aA2); aB2 = fmaf(eB, xm.z, aB2);
        }
#pragma unroll
        for (int off = 16; off; off >>= 1) {
            smA += __shfl_xor_sync(0xffffffffu, smA, off);
            aA0 += __shfl_xor_sync(0xffffffffu, aA0, off);
            aA1 += __shfl_xor_sync(0xffffffffu, aA1, off);
            aA2 += __shfl_xor_sync(0xffffffffu, aA2, off);
            smB += __shfl_xor_sync(0xffffffffu, smB, off);
            aB0 += __shfl_xor_sync(0xffffffffu, aB0, off);
            aB1 += __shfl_xor_sync(0xffffffffu, aB1, off);
            aB2 += __shfl_xor_sync(0xffffffffu, aB2, off);
        }

        const float invA = __fdividef(1.f, smA);
        const float invB = __fdividef(1.f, smB);
        const float mA0 = aA0 * invA, mA1 = aA1 * invA, mA2 = aA2 * invA;
        const float mB0 = aB0 * invB, mB1 = aB1 * invB, mB2 = aB2 * invB;

        const float oA0 = fmaf(sNw[0], mA0, fmaf(sNw[1], mA1, fmaf(sNw[2], mA2, sp[0])));
        const float oA1 = fmaf(sNw[3], mA0, fmaf(sNw[4], mA1, fmaf(sNw[5], mA2, sp[1])));
        const float oA2 = fmaf(sNw[6], mA0, fmaf(sNw[7], mA1, fmaf(sNw[8], mA2, sp[2])));
        const float oB0 = fmaf(sNw[0], mB0, fmaf(sNw[1], mB1, fmaf(sNw[2], mB2, sp[0])));
        const float oB1 = fmaf(sNw[3], mB0, fmaf(sNw[4], mB1, fmaf(sNw[5], mB2, sp[1])));
        const float oB2 = fmaf(sNw[6], mB0, fmaf(sNw[7], mB1, fmaf(sNw[8], mB2, sp[2])));

        // dual MLP: packed float4 weights -> 2 LDS.128 per iter
        float yA0 = 0.f, yA1 = 0.f, yA2 = 0.f;
        float yB0 = 0.f, yB1 = 0.f, yB2 = 0.f;
#pragma unroll
        for (int t = 0; t < HH / 32; t++) {
            const int j = lane + t * 32;
            const float4 w = sW1p[j];
            float hA = fmaf(w.x, oA0, fmaf(w.y, oA1, fmaf(w.z, oA2, w.w)));
            float hB = fmaf(w.x, oB0, fmaf(w.y, oB1, fmaf(w.z, oB2, w.w)));
            hA = fmaxf(hA, 0.f); hB = fmaxf(hB, 0.f);
            const float4 u = sW2p[j];
            yA0 = fmaf(u.x, hA, yA0); yB0 = fmaf(u.x, hB, yB0);
            yA1 = fmaf(u.y, hA, yA1); yB1 = fmaf(u.y, hB, yB1);
            yA2 = fmaf(u.z, hA, yA2); yB2 = fmaf(u.z, hB, yB2);
        }
#pragma unroll
        for (int off = 16; off; off >>= 1) {
            yA0 += __shfl_xor_sync(0xffffffffu, yA0, off);
            yA1 += __shfl_xor_sync(0xffffffffu, yA1, off);
            yA2 += __shfl_xor_sync(0xffffffffu, yA2, off);
            yB0 += __shfl_xor_sync(0xffffffffu, yB0, off);
            yB1 += __shfl_xor_sync(0xffffffffu, yB1, off);
            yB2 += __shfl_xor_sync(0xffffffffu, yB2, off);
        }
        if (lane == 0) {
            float* op = out + (size_t)(b * KOUT + n0q) * 3;
            op[0] = yA0 + b20; op[1] = yA1 + b21; op[2] = yA2 + b22;
            if (has2) {
                float* oq = out + (size_t)(b * KOUT + n1q) * 3;
                oq[0] = yB0 + b20; oq[1] = yB1 + b21; oq[2] = yB2 + b22;
            }
        }
    }

    // ---------------- noise path: block c==31 only (side-1 list is empty) ----
    // Noise rows: ctx is zeroed AFTER v-projection in the reference, so
    // o = Wo·0 + bo = bo exactly (NOT sp = Wo·bv + bo).
    if (c == 31) {
        if (warp == 4) {
            const float o0 = __ldg(bo + 0), o1 = __ldg(bo + 1), o2 = __ldg(bo + 2);
            float y0 = 0.f, y1 = 0.f, y2 = 0.f;
#pragma unroll
            for (int t = 0; t < HH / 32; t++) {
                const int j = lane + t * 32;
                const float4 w = sW1p[j];
                float h = fmaf(w.x, o0, fmaf(w.y, o1, fmaf(w.z, o2, w.w)));
                h = fmaxf(h, 0.f);
                const float4 u = sW2p[j];
                y0 = fmaf(u.x, h, y0);
                y1 = fmaf(u.y, h, y1);
                y2 = fmaf(u.z, h, y2);
            }
#pragma unroll
            for (int off = 16; off; off >>= 1) {
                y0 += __shfl_xor_sync(0xffffffffu, y0, off);
                y1 += __shfl_xor_sync(0xffffffffu, y1, off);
                y2 += __shfl_xor_sync(0xffffffffu, y2, off);
            }
            if (lane == 0) {
                s_y3[0] = y0 + b20;
                s_y3[1] = y1 + b21;
                s_y3[2] = y2 + b22;
            }
        }
        __syncthreads();
        const float y0 = s_y3[0], y1 = s_y3[1], y2 = s_y3[2];
        const int4 L = reinterpret_cast<const int4*>(lab)[tid];   // n = 4*tid < 1024
        const int n0 = tid * 4;
        if (L.x == -1) { float* op = out + (size_t)(b*KOUT + n0    )*3; op[0]=y0; op[1]=y1; op[2]=y2; }
        if (L.y == -1) { float* op = out + (size_t)(b*KOUT + n0 + 1)*3; op[0]=y0; op[1]=y1; op[2]=y2; }
        if (L.z == -1) { float* op = out + (size_t)(b*KOUT + n0 + 2)*3; op[0]=y0; op[1]=y1; op[2]=y2; }
        if (L.w == -1) { float* op = out + (size_t)(b*KOUT + n0 + 3)*3; op[0]=y0; op[1]=y1; op[2]=y2; }
    }
}

// ---------------------------------------------------------------------------
extern "C" void kernel_launch(void* const* d_in, const int* in_sizes, int n_in,
                              void* d_out, int out_size)
{
    const float* x      = (const float*)d_in[0];
    const int*   labels = (const int*)  d_in[1];
    const float* Wq = (const float*)d_in[2];
    const float* bq = (const float*)d_in[3];
    const float* Wk = (const float*)d_in[4];
    const float* bk = (const float*)d_in[5];
    const float* Wv = (const float*)d_in[6];
    const float* bv = (const float*)d_in[7];
    const float* Wo = (const float*)d_in[8];
    const float* bo = (const float*)d_in[9];
    const float* W1 = (const float*)d_in[10];
    const float* b1 = (const float*)d_in[11];
    const float* W2 = (const float*)d_in[12];
    const float* b2 = (const float*)d_in[13];
    float* out = (float*)d_out;

    fused_kernel<<<BATCH * 32, 256>>>(x, labels, Wq, bq, Wk, bk, Wv, bv,
                                      Wo, bo, W1, b1, W2, b2, out);
}

// round 17
// speedup vs baseline: 1.1178x; 1.1178x over previous
#include <cuda_runtime.h>
#include <math.h>

#define BATCH 8
#define NPTS  4096
#define HH    256
#define KOUT  1024
#define CAPH  256           // per-cluster smem capacity (E[cnt]=64 -> 24 sigma)
#define NT    512           // threads per block

// ---------------------------------------------------------------------------
// Single kernel, 256 blocks x 512 threads = 8 batches x 32 cluster-PAIR blocks.
// Block (b,c) owns clusters {2c, 2c+1}; pair membership is ONE compare:
// ((unsigned)l >> 1) == c (noise l=-1 can never match).
// Block c==31 also owns the noise rows (label 63 never occurs -> side-1 empty).
// Noise rows: ctx is zeroed AFTER the v-projection, so o = bo exactly.
// Phase 1: bitmask scan (2 int4 loads/thread) -> two member/query lists.
// Phase 2: parallel gather of member x into smem halves.
// Phase 3: warps 0-7 -> cluster 2c, warps 8-15 -> 2c+1; dual-query rounds,
//          packed-f4 MLP, xor-butterfly reductions. Pre-folded weights:
//   score(x_m) = qk·x_m + qb,   qk = M·x_q + u,  qb = wb·x_q + s0
//   o          = N·mean + p     (valid queries; k/v/ctx never materialized)
// ---------------------------------------------------------------------------
__global__ __launch_bounds__(NT, 2)
void fused_kernel(const float* __restrict__ x,
                  const int*   __restrict__ labels,
                  const float* __restrict__ Wq, const float* __restrict__ bq,
                  const float* __restrict__ Wk, const float* __restrict__ bk,
                  const float* __restrict__ Wv, const float* __restrict__ bv,
                  const float* __restrict__ Wo, const float* __restrict__ bo,
                  const float* __restrict__ W1, const float* __restrict__ b1,
                  const float* __restrict__ W2, const float* __restrict__ b2,
                  float* __restrict__ out)
{
    __shared__ float4 sx[2 * CAPH];       // member x; [0,256) side0, [256,512) side1
    __shared__ short  smidx[2 * CAPH];    // member original row n
    __shared__ int    sq[2 * CAPH];       // (sx idx << 16) | query row n, per side
    __shared__ float4 sW1p[HH];           // (W1[3j], W1[3j+1], W1[3j+2], b1[j])
    __shared__ float4 sW2p[HH];           // (W2[j], W2[HH+j], W2[2HH+j], 0)
    __shared__ float  sM[9], su[3], swb[3], sNw[9], sp3[3], s_s0;
    __shared__ int    s_cnt0, s_cnt1, s_qn0, s_qn1;
    __shared__ float  s_y3[3];

    const int tid  = threadIdx.x;
    const int warp = tid >> 5;
    const int lane = tid & 31;
    const int b    = blockIdx.x >> 5;
    const int c    = blockIdx.x & 31;     // cluster pair {2c, 2c+1}

    const int*   lab = labels + b * NPTS;
    const float* xb  = x + (size_t)b * NPTS * 3;

    // Stage MLP weights packed (threads 0..255, one j each)
    if (tid < HH) {
        const int j = tid;
        sW1p[j] = make_float4(W1[3*j], W1[3*j+1], W1[3*j+2], b1[j]);
        sW2p[j] = make_float4(W2[j], W2[HH + j], W2[2*HH + j], 0.f);
    }
    if (tid == 0) { s_cnt0 = 0; s_cnt1 = 0; s_qn0 = 0; s_qn1 = 0; }
    __syncthreads();

    // Phase 1: one-compare pair scan, 2 int4 loads per thread.
    // chunk t in {0,1}: i = t*512 + tid, rows n = 4i..4i+3 = t*2048 + tid*4 + j
    const int4* lab4 = reinterpret_cast<const int4*>(lab);
    unsigned mask = 0;
#pragma unroll
    for (int t = 0; t < 2; t++) {
        const int4 L = lab4[t * NT + tid];
        mask |= (unsigned)(((unsigned)L.x >> 1) == (unsigned)c) << (t * 4 + 0);
        mask |= (unsigned)(((unsigned)L.y >> 1) == (unsigned)c) << (t * 4 + 1);
        mask |= (unsigned)(((unsigned)L.z >> 1) == (unsigned)c) << (t * 4 + 2);
        mask |= (unsigned)(((unsigned)L.w >> 1) == (unsigned)c) << (t * 4 + 3);
    }
    const int nbase = tid * 4;
    const bool qtid = tid < 256;                          // tid<256 & t==0 <=> n<1024
    while (mask) {
        const int bi = __ffs(mask) - 1;
        mask &= mask - 1;
        const int n    = ((bi >> 2) << 11) + nbase + (bi & 3);
        const int side = lab[n] & 1;                      // L1-hit reload
        const int p    = atomicAdd(side ? &s_cnt1 : &s_cnt0, 1);
        if (p < CAPH) {
            const int idx = side * CAPH + p;
            smidx[idx] = (short)n;
            if (qtid && bi < 4) {                         // <=> n < KOUT
                const int qp = atomicAdd(side ? &s_qn1 : &s_qn0, 1);
                sq[side * CAPH + qp] = n | (idx << 16);
            }
        }
    }

    // Parallel prefold: 28 threads, one folded scalar each.
    if (tid < 28) {
        const float scale = 0.57735026919f;   // 1/sqrt(3)
        const int i = tid;
        if (i < 9) {
            int cc = i / 3, d = i % 3;
            sM[i] = scale * (__ldg(Wq+d)  *__ldg(Wk+cc)
                           + __ldg(Wq+3+d)*__ldg(Wk+3+cc)
                           + __ldg(Wq+6+d)*__ldg(Wk+6+cc));
        } else if (i < 12) {
            int cc = i - 9;
            su[cc] = scale * (__ldg(bq+0)*__ldg(Wk+cc)
                            + __ldg(bq+1)*__ldg(Wk+3+cc)
                            + __ldg(bq+2)*__ldg(Wk+6+cc));
        } else if (i < 15) {
            int cc = i - 12;
            swb[cc] = scale * (__ldg(bk+0)*__ldg(Wq+cc)
                             + __ldg(bk+1)*__ldg(Wq+3+cc)
                             + __ldg(bk+2)*__ldg(Wq+6+cc));
        } else if (i == 15) {
            s_s0 = scale * (__ldg(bk+0)*__ldg(bq+0)
                          + __ldg(bk+1)*__ldg(bq+1)
                          + __ldg(bk+2)*__ldg(bq+2));
        } else if (i < 25) {
            int r = (i - 16) / 3, cc = (i - 16) % 3;
            sNw[i-16] = __ldg(Wo+r*3+0)*__ldg(Wv+cc)
                      + __ldg(Wo+r*3+1)*__ldg(Wv+3+cc)
                      + __ldg(Wo+r*3+2)*__ldg(Wv+6+cc);
        } else {
            int r = i - 25;
            sp3[r] = __ldg(Wo+r*3+0)*__ldg(bv+0)
                   + __ldg(Wo+r*3+1)*__ldg(bv+1)
                   + __ldg(Wo+r*3+2)*__ldg(bv+2) + __ldg(bo+r);
        }
    }
    __syncthreads();

    const int cnt0 = min(s_cnt0, CAPH);
    const int cnt1 = min(s_cnt1, CAPH);

    // Phase 2: pure parallel gather of member x (no atomics)
    if (tid < cnt0) {
        const float* xv = xb + (size_t)smidx[tid] * 3;
        sx[tid] = make_float4(xv[0], xv[1], xv[2], 0.f);
    }
    if (tid < cnt1) {
        const float* xv = xb + (size_t)smidx[CAPH + tid] * 3;
        sx[CAPH + tid] = make_float4(xv[0], xv[1], xv[2], 0.f);
    }
    __syncthreads();

    const float b20 = __ldg(b2 + 0), b21 = __ldg(b2 + 1), b22 = __ldg(b2 + 2);

    // Phase 3: warps 0-7 -> side 0, warps 8-15 -> side 1; dual-query rounds.
    const int side  = warp >> 3;
    const int qn    = side ? s_qn1 : s_qn0;
    const int cnt   = side ? cnt1 : cnt0;
    const int sbase = side * CAPH;

    for (int qq = (warp & 7) * 2; qq < qn; qq += 16) {
        const int  e0   = sq[sbase + qq];
        const bool has2 = (qq + 1) < qn;
        const int  e1   = has2 ? sq[sbase + qq + 1] : e0;
        const int  n0q  = e0 & 0xFFFF, p0 = e0 >> 16;
        const int  n1q  = e1 & 0xFFFF, p1 = e1 >> 16;

        const float4 xqa = sx[p0];
        const float4 xqb = sx[p1];

        const float qkA0 = fmaf(sM[0], xqa.x, fmaf(sM[1], xqa.y, fmaf(sM[2], xqa.z, su[0])));
        const float qkA1 = fmaf(sM[3], xqa.x, fmaf(sM[4], xqa.y, fmaf(sM[5], xqa.z, su[1])));
        const float qkA2 = fmaf(sM[6], xqa.x, fmaf(sM[7], xqa.y, fmaf(sM[8], xqa.z, su[2])));
        const float qbA  = fmaf(swb[0], xqa.x, fmaf(swb[1], xqa.y, fmaf(swb[2], xqa.z, s_s0)));
        const float qkB0 = fmaf(sM[0], xqb.x, fmaf(sM[1], xqb.y, fmaf(sM[2], xqb.z, su[0])));
        const float qkB1 = fmaf(sM[3], xqb.x, fmaf(sM[4], xqb.y, fmaf(sM[5], xqb.z, su[1])));
        const float qkB2 = fmaf(sM[6], xqb.x, fmaf(sM[7], xqb.y, fmaf(sM[8], xqb.z, su[2])));
        const float qbB  = fmaf(swb[0], xqb.x, fmaf(swb[1], xqb.y, fmaf(swb[2], xqb.z, s_s0)));

        // dual plain-exp softmax; one sx load feeds both queries
        float smA = 0.f, aA0 = 0.f, aA1 = 0.f, aA2 = 0.f;
        float smB = 0.f, aB0 = 0.f, aB1 = 0.f, aB2 = 0.f;
        for (int i = lane; i < cnt; i += 32) {
            const float4 xm = sx[sbase + i];
            const float sA = fmaf(qkA0, xm.x, fmaf(qkA1, xm.y, fmaf(qkA2, xm.z, qbA)));
            const float sB = fmaf(qkB0, xm.x, fmaf(qkB1, xm.y, fmaf(qkB2, xm.z, qbB)));
            const float eA = __expf(sA);
            const float eB = __expf(sB);
            smA += eA; smB += eB;
            aA0 = fmaf(eA, xm.x, aA0); aB0 = fmaf(eB, xm.x, aB0);
            aA1 = fmaf(eA, xm.y, aA1); aB1 = fmaf(eB, xm.y, aB1);
            aA2 = fmaf(eA, xm.z, aA2); aB2 = fmaf(eB, xm.z, aB2);
        }
#pragma unroll
        for (int off = 16; off; off >>= 1) {
            smA += __shfl_xor_sync(0xffffffffu, smA, off);
            aA0 += __shfl_xor_sync(0xffffffffu, aA0, off);
            aA1 += __shfl_xor_sync(0xffffffffu, aA1, off);
            aA2 += __shfl_xor_sync(0xffffffffu, aA2, off);
            smB += __shfl_xor_sync(0xffffffffu, smB, off);
            aB0 += __shfl_xor_sync(0xffffffffu, aB0, off);
            aB1 += __shfl_xor_sync(0xffffffffu, aB1, off);
            aB2 += __shfl_xor_sync(0xffffffffu, aB2, off);
        }

        const float invA = __fdividef(1.f, smA);
        const float invB = __fdividef(1.f, smB);
        const float mA0 = aA0 * invA, mA1 = aA1 * invA, mA2 = aA2 * invA;
        const float mB0 = aB0 * invB, mB1 = aB1 * invB, mB2 = aB2 * invB;

        const float oA0 = fmaf(sNw[0], mA0, fmaf(sNw[1], mA1, fmaf(sNw[2], mA2, sp3[0])));
        const float oA1 = fmaf(sNw[3], mA0, fmaf(sNw[4], mA1, fmaf(sNw[5], mA2, sp3[1])));
        const float oA2 = fmaf(sNw[6], mA0, fmaf(sNw[7], mA1, fmaf(sNw[8], mA2, sp3[2])));
        const float oB0 = fmaf(sNw[0], mB0, fmaf(sNw[1], mB1, fmaf(sNw[2], mB2, sp3[0])));
        const float oB1 = fmaf(sNw[3], mB0, fmaf(sNw[4], mB1, fmaf(sNw[5], mB2, sp3[1])));
        const float oB2 = fmaf(sNw[6], mB0, fmaf(sNw[7], mB1, fmaf(sNw[8], mB2, sp3[2])));

        // dual MLP: packed float4 weights -> 2 LDS.128 per iter
        float yA0 = 0.f, yA1 = 0.f, yA2 = 0.f;
        float yB0 = 0.f, yB1 = 0.f, yB2 = 0.f;
#pragma unroll
        for (int t = 0; t < HH / 32; t++) {
            const int j = lane + t * 32;
            const float4 w = sW1p[j];
            float hA = fmaf(w.x, oA0, fmaf(w.y, oA1, fmaf(w.z, oA2, w.w)));
            float hB = fmaf(w.x, oB0, fmaf(w.y, oB1, fmaf(w.z, oB2, w.w)));
            hA = fmaxf(hA, 0.f); hB = fmaxf(hB, 0.f);
            const float4 u = sW2p[j];
            yA0 = fmaf(u.x, hA, yA0); yB0 = fmaf(u.x, hB, yB0);
            yA1 = fmaf(u.y, hA, yA1); yB1 = fmaf(u.y, hB, yB1);
            yA2 = fmaf(u.z, hA, yA2); yB2 = fmaf(u.z, hB, yB2);
        }
#pragma unroll
        for (int off = 16; off; off >>= 1) {
            yA0 += __shfl_xor_sync(0xffffffffu, yA0, off);
            yA1 += __shfl_xor_sync(0xffffffffu, yA1, off);
            yA2 += __shfl_xor_sync(0xffffffffu, yA2, off);
            yB0 += __shfl_xor_sync(0xffffffffu, yB0, off);
            yB1 += __shfl_xor_sync(0xffffffffu, yB1, off);
            yB2 += __shfl_xor_sync(0xffffffffu, yB2, off);
        }
        if (lane == 0) {
            float* op = out + (size_t)(b * KOUT + n0q) * 3;
            op[0] = yA0 + b20; op[1] = yA1 + b21; op[2] = yA2 + b22;
            if (has2) {
                float* oq = out + (size_t)(b * KOUT + n1q) * 3;
                oq[0] = yB0 + b20; oq[1] = yB1 + b21; oq[2] = yB2 + b22;
            }
        }
    }

    // ---------------- noise path: block c==31 only (side-1 list is empty) ----
    // Noise rows: ctx zeroed AFTER v-projection -> o = Wo·0 + bo = bo exactly.
    if (c == 31) {
        if (warp == 8) {
            const float o0 = __ldg(bo + 0), o1 = __ldg(bo + 1), o2 = __ldg(bo + 2);
            float y0 = 0.f, y1 = 0.f, y2 = 0.f;
#pragma unroll
            for (int t = 0; t < HH / 32; t++) {
                const int j = lane + t * 32;
                const float4 w = sW1p[j];
                float h = fmaf(w.x, o0, fmaf(w.y, o1, fmaf(w.z, o2, w.w)));
                h = fmaxf(h, 0.f);
                const float4 u = sW2p[j];
                y0 = fmaf(u.x, h, y0);
                y1 = fmaf(u.y, h, y1);
                y2 = fmaf(u.z, h, y2);
            }
#pragma unroll
            for (int off = 16; off; off >>= 1) {
                y0 += __shfl_xor_sync(0xffffffffu, y0, off);
                y1 += __shfl_xor_sync(0xffffffffu, y1, off);
                y2 += __shfl_xor_sync(0xffffffffu, y2, off);
            }
            if (lane == 0) {
                s_y3[0] = y0 + b20;
                s_y3[1] = y1 + b21;
                s_y3[2] = y2 + b22;
            }
        }
        __syncthreads();
        if (tid < 256) {
            const float y0 = s_y3[0], y1 = s_y3[1], y2 = s_y3[2];
            const int4 L = reinterpret_cast<const int4*>(lab)[tid];  // n = 4*tid < 1024
            const int n0 = tid * 4;
            if (L.x == -1) { float* op = out + (size_t)(b*KOUT + n0    )*3; op[0]=y0; op[1]=y1; op[2]=y2; }
            if (L.y == -1) { float* op = out + (size_t)(b*KOUT + n0 + 1)*3; op[0]=y0; op[1]=y1; op[2]=y2; }
            if (L.z == -1) { float* op = out + (size_t)(b*KOUT + n0 + 2)*3; op[0]=y0; op[1]=y1; op[2]=y2; }
            if (L.w == -1) { float* op = out + (size_t)(b*KOUT + n0 + 3)*3; op[0]=y0; op[1]=y1; op[2]=y2; }
        }
    }
}

// ---------------------------------------------------------------------------
extern "C" void kernel_launch(void* const* d_in, const int* in_sizes, int n_in,
                              void* d_out, int out_size)
{
    const float* x      = (const float*)d_in[0];
    const int*   labels = (const int*)  d_in[1];
    const float* Wq = (const float*)d_in[2];
    const float* bq = (const float*)d_in[3];
    const float* Wk = (const float*)d_in[4];
    const float* bk = (const float*)d_in[5];
    const float* Wv = (const float*)d_in[6];
    const float* bv = (const float*)d_in[7];
    const float* Wo = (const float*)d_in[8];
    const float* bo = (const float*)d_in[9];
    const float* W1 = (const float*)d_in[10];
    const float* b1 = (const float*)d_in[11];
    const float* W2 = (const float*)d_in[12];
    const float* b2 = (const float*)d_in[13];
    float* out = (float*)d_out;

    fused_kernel<<<BATCH * 32, NT>>>(x, labels, Wq, bq, Wk, bk, Wv, bv,
                                     Wo, bo, W1, b1, W2, b2, out);
}